// round 5
// baseline (speedup 1.0000x reference)
#include <cuda_runtime.h>
#include <cuda_bf16.h>
#include <cstdint>

#define B_   4
#define V_   778
#define F_   1538
#define NT   3076          // 2*F_ (faces + reversed)
#define RW   256
#define NPIX (RW * RW)
#define FARV 10.0f
#define TILE 32
#define TC   256
#define S_   16            // triangle slices per batch
#define SLICE ((NT + S_ - 1) / S_)   // 193  (single chunk per block)
#define HX   0.12109375f   // NDC half-extent of 31px tile span (31/256)

// ---------------- scratch (static device globals; no allocation) -------------
__device__ float4   g_e0  [B_ * NT];   // U0,V0,W0,E0
__device__ float4   g_e1  [B_ * NT];   // U1,V1,W1,E1
__device__ float4   g_e2  [B_ * NT];   // U2,V2,W2,E2
__device__ float4   g_gi  [B_ * NT];   // Gx,Gy,Gc,-
__device__ float4   g_bbox[B_ * NT];   // xmin,xmax,ymin,ymax
__device__ unsigned g_inv [B_ * NPIX]; // per-pixel max(inv) as ordered uint
__device__ unsigned g_mx  [B_];
__device__ unsigned g_mn  [B_];

// explicit LOP3s
__device__ __forceinline__ unsigned or3(unsigned a, unsigned b, unsigned c) {
    unsigned r;
    asm("lop3.b32 %0, %1, %2, %3, 0xFE;" : "=r"(r) : "r"(a), "r"(b), "r"(c));
    return r;   // a | b | c
}
__device__ __forceinline__ unsigned sign_merge(unsigned iv, unsigned s) {
    unsigned r;
    asm("lop3.b32 %0, %1, %2, %3, 0xF8;" : "=r"(r) : "r"(iv), "r"(s), "n"(0x80000000));
    return r;   // iv | (s & 0x80000000)
}

// ---------------- projection helper ------------------------------------------
__device__ __forceinline__ float3 proj_vert(const float* __restrict__ verts,
                                            const float* __restrict__ Rb,
                                            const float* __restrict__ tb,
                                            const float* __restrict__ Kb,
                                            const float* __restrict__ db,
                                            int vglob) {
    const float* p = verts + vglob * 3;
    float px = p[0], py = p[1], pz = p[2];
    float x = Rb[0]*px + Rb[1]*py + Rb[2]*pz + tb[0];
    float y = Rb[3]*px + Rb[4]*py + Rb[5]*pz + tb[1];
    float z = Rb[6]*px + Rb[7]*py + Rb[8]*pz + tb[2];

    float zi = z + 1e-9f;
    float x_ = x / zi, y_ = y / zi;
    float k1 = db[0], k2 = db[1], p1 = db[2], p2 = db[3], k3 = db[4];
    float r2 = x_*x_ + y_*y_;
    float radial = 1.0f + k1*r2 + k2*r2*r2 + k3*r2*r2*r2;
    float x2 = x_*radial + 2.0f*p1*x_*y_ + p2*(r2 + 2.0f*x_*x_);
    float y2 = y_*radial + p1*(r2 + 2.0f*y_*y_) + 2.0f*p2*x_*y_;
    float u  = Kb[0]*x2 + Kb[1]*y2 + Kb[2];
    float vv = Kb[3]*x2 + Kb[4]*y2 + Kb[5];
    vv = 256.0f - vv;
    u  = 2.0f * (u  - 128.0f) / 256.0f;
    vv = 2.0f * (vv - 128.0f) / 256.0f;
    return make_float3(u, vv, z);
}

// ---------------- K1: fused setup (project inline) + scratch clear -----------
__global__ void __launch_bounds__(256) k_prep(const float* __restrict__ verts,
                                              const int*   __restrict__ faces,
                                              const float* __restrict__ intr,
                                              const float* __restrict__ R,
                                              const float* __restrict__ t,
                                              const float* __restrict__ dist) {
    int gid = blockIdx.x * 256 + threadIdx.x;

    if (gid < B_ * NT) {
        int b  = gid / NT;
        int tt = gid - b * NT;
        const float* Rb = R    + b * 9;
        const float* tb = t    + b * 3;
        const float* Kb = intr + b * 9;
        const float* db = dist + b * 5;

        int base = (b * F_ + (tt < F_ ? tt : tt - F_)) * 3;
        int i0 = faces[base + 0], i1 = faces[base + 1], i2 = faces[base + 2];
        if (tt >= F_) { int tmp = i0; i0 = i2; i2 = tmp; }

        float3 A  = proj_vert(verts, Rb, tb, Kb, db, b * V_ + i0);
        float3 Bv = proj_vert(verts, Rb, tb, Kb, db, b * V_ + i1);
        float3 Cv = proj_vert(verts, Rb, tb, Kb, db, b * V_ + i2);
        float ax = A.x,  ay = A.y,  az = A.z;
        float bx = Bv.x, by = Bv.y, bz = Bv.z;
        float cx = Cv.x, cy = Cv.y, cz = Cv.z;

        float den = (bx - ax) * (cy - ay) - (by - ay) * (cx - ax);
        bool ok = (fabsf(den) > 1e-8f) && (az > 1e-8f) && (bz > 1e-8f) && (cz > 1e-8f);

        float4 e0, e1, e2, gi, bb;
        if (!ok) {
            e0 = make_float4(0.f, 0.f, -1e30f, 0.f);
            e1 = make_float4(0.f, 0.f, 0.f, 0.f);
            e2 = make_float4(0.f, 0.f, 0.f, 0.f);
            gi = make_float4(0.f, 0.f, 0.f, 0.f);
            bb = make_float4(2e30f, -2e30f, 2e30f, -2e30f);
        } else {
            float id = 1.0f / den;
            float U0 = (by - cy) * id, V0 = (cx - bx) * id;
            float W0 = -(U0 * cx + V0 * cy);
            float U1 = (cy - ay) * id, V1 = (ax - cx) * id;
            float W1 = -(U1 * cx + V1 * cy);
            float U2 = -(U0 + U1), V2 = -(V0 + V1), W2 = 1.0f - W0 - W1;
            float ra = 1.0f / az, rb = 1.0f / bz, rc = 1.0f / cz;
            float dA = ra - rc, dB = rb - rc;
            float Gx = U0 * dA + U1 * dB;
            float Gy = V0 * dA + V1 * dB;
            float Gc = rc + W0 * dA + W1 * dB;
            e0 = make_float4(U0, V0, W0, (fabsf(U0) + fabsf(V0)) * HX);
            e1 = make_float4(U1, V1, W1, (fabsf(U1) + fabsf(V1)) * HX);
            e2 = make_float4(U2, V2, W2, (fabsf(U2) + fabsf(V2)) * HX);
            gi = make_float4(Gx, Gy, Gc, 0.f);
            bb = make_float4(fminf(ax, fminf(bx, cx)), fmaxf(ax, fmaxf(bx, cx)),
                             fminf(ay, fminf(by, cy)), fmaxf(ay, fmaxf(by, cy)));
        }
        g_e0[gid] = e0; g_e1[gid] = e1; g_e2[gid] = e2;
        g_gi[gid] = gi; g_bbox[gid] = bb;
    }

    // vectorized clear of g_inv (65536 uint4 = 1MB)
    reinterpret_cast<uint4*>(g_inv)[gid] = make_uint4(0u, 0u, 0u, 0u);
    if (gid < B_) { g_mx[gid] = 0u; g_mn[gid] = __float_as_uint(FARV); }
}

// ---------------- K2: classified tiled rasterizer ----------------------------
// tile 32x32 px, 256 threads, 4 px/thread, 16 triangle slices; single chunk
__global__ void __launch_bounds__(256) k_raster() {
    __shared__ float4 sp0[TC], sp1[TC], sp2[TC];  // (Ui,Vi,Wi, Gx/Gy/Gc)
    __shared__ float4 sfl[TC];
    __shared__ int    nP, nF;

    int bz = blockIdx.z;
    int b  = bz & (B_ - 1);
    int sl = bz >> 2;
    int t0 = sl * SLICE;
    int t1 = min(NT, t0 + SLICE);

    int tid = threadIdx.x;
    int row = tid >> 3;
    int xg  = tid & 7;
    int tx  = blockIdx.x * TILE;
    int ty  = blockIdx.y * TILE;
    int ix0 = tx + xg * 4;
    int iy  = ty + row;

    float y  = 2.0f * (iy + 0.5f) / 256.0f - 1.0f;
    float x0 = 2.0f * (ix0 + 0.5f) / 256.0f - 1.0f;
    float x1 = 2.0f * (ix0 + 1.5f) / 256.0f - 1.0f;
    float x2 = 2.0f * (ix0 + 2.5f) / 256.0f - 1.0f;
    float x3 = 2.0f * (ix0 + 3.5f) / 256.0f - 1.0f;

    float xlo = 2.0f * (tx +  0.5f) / 256.0f - 1.0f;
    float xhi = 2.0f * (tx + 31.5f) / 256.0f - 1.0f;
    float ylo = 2.0f * (ty +  0.5f) / 256.0f - 1.0f;
    float yhi = 2.0f * (ty + 31.5f) / 256.0f - 1.0f;
    float xc  = 0.5f * (xlo + xhi);
    float yc  = 0.5f * (ylo + yhi);

    const float4* e0p  = g_e0   + b * NT;
    const float4* e1p  = g_e1   + b * NT;
    const float4* e2p  = g_e2   + b * NT;
    const float4* gip  = g_gi   + b * NT;
    const float4* bbox = g_bbox + b * NT;

    if (tid == 0) { nP = 0; nF = 0; }
    __syncthreads();

    int tI = t0 + tid;
    if (tI < t1) {
        float4 bb = bbox[tI];
        if (bb.x <= xhi && bb.y >= xlo && bb.z <= yhi && bb.w >= ylo) {
            float4 r0 = e0p[tI];
            float4 r1 = e1p[tI];
            float4 r2 = e2p[tI];
            float cv0 = fmaf(r0.x, xc, fmaf(r0.y, yc, r0.z));
            float cv1 = fmaf(r1.x, xc, fmaf(r1.y, yc, r1.z));
            float cv2 = fmaf(r2.x, xc, fmaf(r2.y, yc, r2.z));
            float me0 = fmaf(r0.w, 2e-6f, 1e-6f);
            float me1 = fmaf(r1.w, 2e-6f, 1e-6f);
            float me2 = fmaf(r2.w, 2e-6f, 1e-6f);

            bool rej = (cv0 + r0.w < -me0) || (cv1 + r1.w < -me1) ||
                       (cv2 + r2.w < -me2);
            if (!rej) {
                float4 gi = gip[tI];
                bool full = (cv0 - r0.w > me0) && (cv1 - r1.w > me1) &&
                            (cv2 - r2.w > me2);
                if (full) {
                    int s = atomicAdd(&nF, 1);
                    sfl[s] = gi;
                } else {
                    int s = atomicAdd(&nP, 1);
                    sp0[s] = make_float4(r0.x, r0.y, r0.z, gi.x);
                    sp1[s] = make_float4(r1.x, r1.y, r1.z, gi.y);
                    sp2[s] = make_float4(r2.x, r2.y, r2.z, gi.z);
                }
            }
        }
    }
    __syncthreads();
    int np = nP, nf = nF;

    float m0 = 0.f, m1 = 0.f, m2 = 0.f, m3 = 0.f;

    // partial: 4 FFMA + 2 LOP3 + 1 FMNMX per pixel
    for (int j = 0; j < np; j++) {
        float4 a = sp0[j];   // U0,V0,W0,Gx
        float4 c = sp1[j];   // U1,V1,W1,Gy
        float4 d = sp2[j];   // U2,V2,W2,Gc
        float ty0 = fmaf(a.y, y, a.z);
        float ty1 = fmaf(c.y, y, c.z);
        float ty2 = fmaf(d.y, y, d.z);
        float tyi = fmaf(c.w, y, d.w);
        {
            float w0 = fmaf(a.x, x0, ty0), w1 = fmaf(c.x, x0, ty1), w2 = fmaf(d.x, x0, ty2);
            float iv = fmaf(a.w, x0, tyi);
            unsigned s = or3(__float_as_uint(w0), __float_as_uint(w1), __float_as_uint(w2));
            m0 = fmaxf(m0, __uint_as_float(sign_merge(__float_as_uint(iv), s)));
        }
        {
            float w0 = fmaf(a.x, x1, ty0), w1 = fmaf(c.x, x1, ty1), w2 = fmaf(d.x, x1, ty2);
            float iv = fmaf(a.w, x1, tyi);
            unsigned s = or3(__float_as_uint(w0), __float_as_uint(w1), __float_as_uint(w2));
            m1 = fmaxf(m1, __uint_as_float(sign_merge(__float_as_uint(iv), s)));
        }
        {
            float w0 = fmaf(a.x, x2, ty0), w1 = fmaf(c.x, x2, ty1), w2 = fmaf(d.x, x2, ty2);
            float iv = fmaf(a.w, x2, tyi);
            unsigned s = or3(__float_as_uint(w0), __float_as_uint(w1), __float_as_uint(w2));
            m2 = fmaxf(m2, __uint_as_float(sign_merge(__float_as_uint(iv), s)));
        }
        {
            float w0 = fmaf(a.x, x3, ty0), w1 = fmaf(c.x, x3, ty1), w2 = fmaf(d.x, x3, ty2);
            float iv = fmaf(a.w, x3, tyi);
            unsigned s = or3(__float_as_uint(w0), __float_as_uint(w1), __float_as_uint(w2));
            m3 = fmaxf(m3, __uint_as_float(sign_merge(__float_as_uint(iv), s)));
        }
    }

    // full-accept: every pixel valid -> just interpolate inv and fmax
    #pragma unroll 2
    for (int j = 0; j < nf; j++) {
        float4 f = sfl[j];
        float tyi = fmaf(f.y, y, f.z);
        m0 = fmaxf(m0, fmaf(f.x, x0, tyi));
        m1 = fmaxf(m1, fmaf(f.x, x1, tyi));
        m2 = fmaxf(m2, fmaf(f.x, x2, tyi));
        m3 = fmaxf(m3, fmaf(f.x, x3, tyi));
    }

    unsigned* dst = g_inv + b * NPIX + iy * RW + ix0;
    if (m0 > 0.f) atomicMax(dst + 0, __float_as_uint(m0));
    if (m1 > 0.f) atomicMax(dst + 1, __float_as_uint(m1));
    if (m2 > 0.f) atomicMax(dst + 2, __float_as_uint(m2));
    if (m3 > 0.f) atomicMax(dst + 3, __float_as_uint(m3));
}

// ---------------- K3: inv -> z, mask, per-batch min/max (scalar, full chip) --
__global__ void __launch_bounds__(256) k_zpass(float* __restrict__ dep,
                                               float* __restrict__ mask) {
    __shared__ float smx[256], smn[256];
    int idx = blockIdx.x * 256 + threadIdx.x;       // 0..262143
    int b   = idx >> 16;
    int tid = threadIdx.x;

    unsigned mi = g_inv[idx];
    bool cov = mi != 0u;
    float z  = cov ? fminf(FARV, 1.0f / __uint_as_float(mi)) : FARV;

    dep [idx] = z;
    mask[idx] = cov ? 1.0f : 0.0f;

    smx[tid] = (cov && z < FARV) ? z : 0.0f;
    smn[tid] = z;
    __syncthreads();
    for (int s = 128; s > 0; s >>= 1) {
        if (tid < s) {
            smx[tid] = fmaxf(smx[tid], smx[tid + s]);
            smn[tid] = fminf(smn[tid], smn[tid + s]);
        }
        __syncthreads();
    }
    if (tid == 0) {
        atomicMax(&g_mx[b], __float_as_uint(smx[0]));
        atomicMin(&g_mn[b], __float_as_uint(smn[0]));
    }
}

// ---------------- K4: depth normalization (scalar, full chip) ----------------
__global__ void __launch_bounds__(256) k_finalize(float* __restrict__ dep) {
    int idx = blockIdx.x * 256 + threadIdx.x;
    int b   = idx >> 16;
    float mx = __uint_as_float(g_mx[b]);
    float rd = 1.0f / (mx - __uint_as_float(g_mn[b]) + 1e-4f);
    float z  = dep[idx];
    dep[idx] = fminf(fmaxf((mx - z) * rd, 0.0f), 1.0f);
}

// ---------------- launch ------------------------------------------------------
extern "C" void kernel_launch(void* const* d_in, const int* in_sizes, int n_in,
                              void* d_out, int out_size) {
    const float* vertices = (const float*)d_in[0];
    const int*   faces    = (const int*)  d_in[1];
    const float* intr     = (const float*)d_in[2];
    const float* R        = (const float*)d_in[3];
    const float* t        = (const float*)d_in[4];
    const float* dist     = (const float*)d_in[5];

    float* out  = (float*)d_out;
    float* dep  = out;
    float* mask = out + B_ * NPIX;

    k_prep<<<256, 256>>>(vertices, faces, intr, R, t, dist);
    dim3 grid(RW / TILE, RW / TILE, B_ * S_);
    k_raster<<<grid, 256>>>();
    k_zpass<<<1024, 256>>>(dep, mask);
    k_finalize<<<1024, 256>>>(dep);
}

// round 6
// speedup vs baseline: 1.6149x; 1.6149x over previous
#include <cuda_runtime.h>
#include <cuda_bf16.h>
#include <cstdint>

#define B_   4
#define V_   778
#define F_   1538          // single-sided: reversed copies are numerically identical
#define RW   256
#define NPIX (RW * RW)
#define FARV 10.0f
#define TILE 16
#define TC   256
#define S_   8             // triangle slices per batch
#define SLICE ((F_ + S_ - 1) / S_)   // 193  (single chunk per block)
#define HX   0.05859375f   // NDC half-extent of 15px tile span (15/256)

// ---------------- scratch (static device globals; no allocation) -------------
__device__ float4   g_e0  [B_ * F_];   // U0,V0,W0,E0
__device__ float4   g_e1  [B_ * F_];   // U1,V1,W1,E1
__device__ float4   g_e2  [B_ * F_];   // U2,V2,W2,E2
__device__ float4   g_gi  [B_ * F_];   // Gx,Gy,Gc,-
__device__ float4   g_bbox[B_ * F_];   // xmin,xmax,ymin,ymax
__device__ unsigned g_inv [B_ * NPIX]; // per-pixel max(inv) as ordered uint
__device__ unsigned g_mx  [B_];
__device__ unsigned g_mn  [B_];

// ---------------- projection helper ------------------------------------------
__device__ __forceinline__ float3 proj_vert(const float* __restrict__ verts,
                                            const float* __restrict__ Rb,
                                            const float* __restrict__ tb,
                                            const float* __restrict__ Kb,
                                            const float* __restrict__ db,
                                            int vglob) {
    const float* p = verts + vglob * 3;
    float px = p[0], py = p[1], pz = p[2];
    float x = Rb[0]*px + Rb[1]*py + Rb[2]*pz + tb[0];
    float y = Rb[3]*px + Rb[4]*py + Rb[5]*pz + tb[1];
    float z = Rb[6]*px + Rb[7]*py + Rb[8]*pz + tb[2];

    float zi = z + 1e-9f;
    float x_ = x / zi, y_ = y / zi;
    float k1 = db[0], k2 = db[1], p1 = db[2], p2 = db[3], k3 = db[4];
    float r2 = x_*x_ + y_*y_;
    float radial = 1.0f + k1*r2 + k2*r2*r2 + k3*r2*r2*r2;
    float x2 = x_*radial + 2.0f*p1*x_*y_ + p2*(r2 + 2.0f*x_*x_);
    float y2 = y_*radial + p1*(r2 + 2.0f*y_*y_) + 2.0f*p2*x_*y_;
    float u  = Kb[0]*x2 + Kb[1]*y2 + Kb[2];
    float vv = Kb[3]*x2 + Kb[4]*y2 + Kb[5];
    vv = 256.0f - vv;
    u  = 2.0f * (u  - 128.0f) / 256.0f;
    vv = 2.0f * (vv - 128.0f) / 256.0f;
    return make_float3(u, vv, z);
}

// ---------------- K1: fused setup (project inline) + scratch clear -----------
__global__ void __launch_bounds__(256) k_prep(const float* __restrict__ verts,
                                              const int*   __restrict__ faces,
                                              const float* __restrict__ intr,
                                              const float* __restrict__ R,
                                              const float* __restrict__ t,
                                              const float* __restrict__ dist) {
    int gid = blockIdx.x * 256 + threadIdx.x;

    if (gid < B_ * F_) {
        int b  = gid / F_;
        int tt = gid - b * F_;
        const float* Rb = R    + b * 9;
        const float* tb = t    + b * 3;
        const float* Kb = intr + b * 9;
        const float* db = dist + b * 5;

        int base = gid * 3;           // (b*F_ + tt)*3
        int i0 = faces[base + 0], i1 = faces[base + 1], i2 = faces[base + 2];

        float3 A  = proj_vert(verts, Rb, tb, Kb, db, b * V_ + i0);
        float3 Bv = proj_vert(verts, Rb, tb, Kb, db, b * V_ + i1);
        float3 Cv = proj_vert(verts, Rb, tb, Kb, db, b * V_ + i2);
        float ax = A.x,  ay = A.y,  az = A.z;
        float bx = Bv.x, by = Bv.y, bz = Bv.z;
        float cx = Cv.x, cy = Cv.y, cz = Cv.z;

        float den = (bx - ax) * (cy - ay) - (by - ay) * (cx - ax);
        bool ok = (fabsf(den) > 1e-8f) && (az > 1e-8f) && (bz > 1e-8f) && (cz > 1e-8f);

        float4 e0, e1, e2, gi, bb;
        if (!ok) {
            e0 = make_float4(0.f, 0.f, -1e30f, 0.f);
            e1 = make_float4(0.f, 0.f, 0.f, 0.f);
            e2 = make_float4(0.f, 0.f, 0.f, 0.f);
            gi = make_float4(0.f, 0.f, 0.f, 0.f);
            bb = make_float4(2e30f, -2e30f, 2e30f, -2e30f);
        } else {
            float id = 1.0f / den;
            float U0 = (by - cy) * id, V0 = (cx - bx) * id;
            float W0 = -(U0 * cx + V0 * cy);
            float U1 = (cy - ay) * id, V1 = (ax - cx) * id;
            float W1 = -(U1 * cx + V1 * cy);
            float U2 = -(U0 + U1), V2 = -(V0 + V1), W2 = 1.0f - W0 - W1;
            float ra = 1.0f / az, rb = 1.0f / bz, rc = 1.0f / cz;
            float dA = ra - rc, dB = rb - rc;
            float Gx = U0 * dA + U1 * dB;
            float Gy = V0 * dA + V1 * dB;
            float Gc = rc + W0 * dA + W1 * dB;
            e0 = make_float4(U0, V0, W0, (fabsf(U0) + fabsf(V0)) * HX);
            e1 = make_float4(U1, V1, W1, (fabsf(U1) + fabsf(V1)) * HX);
            e2 = make_float4(U2, V2, W2, (fabsf(U2) + fabsf(V2)) * HX);
            gi = make_float4(Gx, Gy, Gc, 0.f);
            bb = make_float4(fminf(ax, fminf(bx, cx)), fmaxf(ax, fmaxf(bx, cx)),
                             fminf(ay, fminf(by, cy)), fmaxf(ay, fmaxf(by, cy)));
        }
        g_e0[gid] = e0; g_e1[gid] = e1; g_e2[gid] = e2;
        g_gi[gid] = gi; g_bbox[gid] = bb;
    }

    // vectorized clear of g_inv (65536 uint4 = 1MB)
    reinterpret_cast<uint4*>(g_inv)[gid] = make_uint4(0u, 0u, 0u, 0u);
    if (gid < B_) { g_mx[gid] = 0u; g_mn[gid] = __float_as_uint(FARV); }
}

// ---------------- K2: classified tiled rasterizer ----------------------------
// tile 16x16 px, 256 threads, 1 px/thread, 8 triangle slices; single chunk
__global__ void __launch_bounds__(256) k_raster() {
    __shared__ float4 spA[TC], spB[TC];   // (U0,V0,W0,U1) (V1,W1,Gx,Gy)
    __shared__ float  spC[TC];            // Gc
    __shared__ float4 sfl[TC];            // Gx,Gy,Gc
    __shared__ int    nP, nF;

    int bz = blockIdx.z;
    int b  = bz & (B_ - 1);
    int sl = bz >> 2;
    int t0 = sl * SLICE;
    int t1 = min(F_, t0 + SLICE);

    int tid = threadIdx.x;
    int tx  = blockIdx.x * TILE;
    int ty  = blockIdx.y * TILE;
    int ix  = tx + (tid & 15);
    int iy  = ty + (tid >> 4);

    float x = 2.0f * (ix + 0.5f) / 256.0f - 1.0f;
    float y = 2.0f * (iy + 0.5f) / 256.0f - 1.0f;

    float xlo = 2.0f * (tx +  0.5f) / 256.0f - 1.0f;
    float xhi = 2.0f * (tx + 15.5f) / 256.0f - 1.0f;
    float ylo = 2.0f * (ty +  0.5f) / 256.0f - 1.0f;
    float yhi = 2.0f * (ty + 15.5f) / 256.0f - 1.0f;
    float xc  = 0.5f * (xlo + xhi);
    float yc  = 0.5f * (ylo + yhi);

    const float4* e0p  = g_e0   + b * F_;
    const float4* e1p  = g_e1   + b * F_;
    const float4* e2p  = g_e2   + b * F_;
    const float4* gip  = g_gi   + b * F_;
    const float4* bbox = g_bbox + b * F_;

    if (tid == 0) { nP = 0; nF = 0; }
    __syncthreads();

    int tI = t0 + tid;
    if (tI < t1) {
        float4 bb = bbox[tI];
        if (bb.x <= xhi && bb.y >= xlo && bb.z <= yhi && bb.w >= ylo) {
            float4 r0 = e0p[tI];
            float4 r1 = e1p[tI];
            float4 r2 = e2p[tI];
            float cv0 = fmaf(r0.x, xc, fmaf(r0.y, yc, r0.z));
            float cv1 = fmaf(r1.x, xc, fmaf(r1.y, yc, r1.z));
            float cv2 = fmaf(r2.x, xc, fmaf(r2.y, yc, r2.z));
            float me0 = fmaf(r0.w, 2e-6f, 1e-6f);
            float me1 = fmaf(r1.w, 2e-6f, 1e-6f);
            float me2 = fmaf(r2.w, 2e-6f, 1e-6f);

            bool rej = (cv0 + r0.w < -me0) || (cv1 + r1.w < -me1) ||
                       (cv2 + r2.w < -me2);
            if (!rej) {
                float4 gi = gip[tI];
                bool full = (cv0 - r0.w > me0) && (cv1 - r1.w > me1) &&
                            (cv2 - r2.w > me2);
                if (full) {
                    int s = atomicAdd(&nF, 1);
                    sfl[s] = gi;
                } else {
                    int s = atomicAdd(&nP, 1);
                    spA[s] = make_float4(r0.x, r0.y, r0.z, r1.x);
                    spB[s] = make_float4(r1.y, r1.z, gi.x, gi.y);
                    spC[s] = gi.z;
                }
            }
        }
    }
    __syncthreads();
    int np = nP, nf = nF;

    float m = 0.f;

    // partial: per-pixel test, R4-proven form
    for (int j = 0; j < np; j++) {
        float4 a = spA[j];
        float4 c = spB[j];
        float gc = spC[j];
        float w0 = fmaf(a.x, x, fmaf(a.y, y, a.z));
        float w1 = fmaf(a.w, x, fmaf(c.x, y, c.y));
        float w2 = (1.0f - w0) - w1;
        float iv = fmaf(c.z, x, fmaf(c.w, y, gc));
        unsigned s = __float_as_uint(w0) | __float_as_uint(w1) | __float_as_uint(w2);
        m = fmaxf(m, __uint_as_float(__float_as_uint(iv) | (s & 0x80000000u)));
    }

    // full-accept: every pixel valid -> just interpolate inv and fmax
    #pragma unroll 2
    for (int j = 0; j < nf; j++) {
        float4 f = sfl[j];
        m = fmaxf(m, fmaf(f.x, x, fmaf(f.y, y, f.z)));
    }

    if (m > 0.f) atomicMax(g_inv + b * NPIX + iy * RW + ix, __float_as_uint(m));
}

// ---------------- K3: inv -> z, mask, per-batch min/max (float4) -------------
__global__ void __launch_bounds__(256) k_zpass(float* __restrict__ dep,
                                               float* __restrict__ mask) {
    __shared__ float smx[256], smn[256];
    int idx4 = blockIdx.x * 256 + threadIdx.x;      // 0..65535
    int b    = idx4 >> 14;
    int tid  = threadIdx.x;

    uint4 mi = reinterpret_cast<const uint4*>(g_inv)[idx4];
    float z0 = mi.x ? fminf(FARV, 1.0f / __uint_as_float(mi.x)) : FARV;
    float z1 = mi.y ? fminf(FARV, 1.0f / __uint_as_float(mi.y)) : FARV;
    float z2 = mi.z ? fminf(FARV, 1.0f / __uint_as_float(mi.z)) : FARV;
    float z3 = mi.w ? fminf(FARV, 1.0f / __uint_as_float(mi.w)) : FARV;

    reinterpret_cast<float4*>(dep)[idx4]  = make_float4(z0, z1, z2, z3);
    reinterpret_cast<float4*>(mask)[idx4] = make_float4(mi.x ? 1.f : 0.f,
                                                        mi.y ? 1.f : 0.f,
                                                        mi.z ? 1.f : 0.f,
                                                        mi.w ? 1.f : 0.f);
    float fx0 = (mi.x && z0 < FARV) ? z0 : 0.f;
    float fx1 = (mi.y && z1 < FARV) ? z1 : 0.f;
    float fx2 = (mi.z && z2 < FARV) ? z2 : 0.f;
    float fx3 = (mi.w && z3 < FARV) ? z3 : 0.f;

    smx[tid] = fmaxf(fmaxf(fx0, fx1), fmaxf(fx2, fx3));
    smn[tid] = fminf(fminf(z0, z1), fminf(z2, z3));
    __syncthreads();
    for (int s = 128; s > 0; s >>= 1) {
        if (tid < s) {
            smx[tid] = fmaxf(smx[tid], smx[tid + s]);
            smn[tid] = fminf(smn[tid], smn[tid + s]);
        }
        __syncthreads();
    }
    if (tid == 0) {
        atomicMax(&g_mx[b], __float_as_uint(smx[0]));
        atomicMin(&g_mn[b], __float_as_uint(smn[0]));
    }
}

// ---------------- K4: depth normalization (scalar, full chip) ----------------
__global__ void __launch_bounds__(256) k_finalize(float* __restrict__ dep) {
    int idx = blockIdx.x * 256 + threadIdx.x;
    int b   = idx >> 16;
    float mx = __uint_as_float(g_mx[b]);
    float rd = 1.0f / (mx - __uint_as_float(g_mn[b]) + 1e-4f);
    float z  = dep[idx];
    dep[idx] = fminf(fmaxf((mx - z) * rd, 0.0f), 1.0f);
}

// ---------------- launch ------------------------------------------------------
extern "C" void kernel_launch(void* const* d_in, const int* in_sizes, int n_in,
                              void* d_out, int out_size) {
    const float* vertices = (const float*)d_in[0];
    const int*   faces    = (const int*)  d_in[1];
    const float* intr     = (const float*)d_in[2];
    const float* R        = (const float*)d_in[3];
    const float* t        = (const float*)d_in[4];
    const float* dist     = (const float*)d_in[5];

    float* out  = (float*)d_out;
    float* dep  = out;
    float* mask = out + B_ * NPIX;

    k_prep<<<256, 256>>>(vertices, faces, intr, R, t, dist);
    dim3 grid(RW / TILE, RW / TILE, B_ * S_);
    k_raster<<<grid, 256>>>();
    k_zpass<<<256, 256>>>(dep, mask);
    k_finalize<<<1024, 256>>>(dep);
}